// round 2
// baseline (speedup 1.0000x reference)
#include <cuda_runtime.h>
#include <math.h>

// Problem dimensions (fixed per reference setup_inputs)
#define M_TOTAL 16384   // B*S = 8*2048
#define DT      1024
#define DL      768
#define LBL     4096
#define THRESH  0.4f

// Scratch (no allocations allowed -> __device__ globals)
__device__ float g_t[(size_t)M_TOTAL * DL];   // 48 MB: projected text
__device__ float g_w[(size_t)M_TOTAL * LBL];  // 256 MB: exp(thresholded sigmoid)

// Tiling
#define BM 128
#define BN 128
#define BK 8
#define TM 8
#define TN 8
// 256 threads, 16x16 thread grid, each thread computes an 8x8 C sub-tile.
// Double-buffered smem, register-staged global prefetch.

// MODE 0: C = A*B^T + bias          (A=text [M,DT], B=W [DL,DT] K-major) -> g_t
// MODE 1: w = exp(thr(sigmoid(.)))  (A=g_t [M,DL], B=labels [L,DL] K-major) -> g_w
// MODE 2: out = (A*B)/rowsum(A)     (A=g_w [M,L],  B=labels [L,DL] N-major) -> out
template<int KDIM, int NDIM, int MODE>
__global__ __launch_bounds__(256, 2)
void gemm_k(const float* __restrict__ Ain,
            const float* __restrict__ Bin,
            const float* __restrict__ bias,
            float* __restrict__ Cout)
{
    __shared__ float As[2][BK][BM];
    __shared__ float Bs[2][BK][BN];

    const float* A = Ain;
    if (MODE == 1) A = g_t;
    if (MODE == 2) A = g_w;
    float* C = Cout;
    if (MODE == 0) C = g_t;
    if (MODE == 1) C = g_w;

    const int tid = threadIdx.x;
    const int tx = tid & 15;        // 0..15 -> N direction
    const int ty = tid >> 4;        // 0..15 -> M direction
    const int mBase = blockIdx.y * BM;
    const int nBase = blockIdx.x * BN;

    // A tile loader: 128 rows x 8 k, one float4 per thread (K-major global)
    const int ar = tid >> 1;           // 0..127
    const int ac = (tid & 1) * 4;      // 0 or 4
    const float* Aptr = A + (size_t)(mBase + ar) * KDIM + ac;

    // B tile loaders
    const float* BptrK = Bin + (size_t)(nBase + ar) * KDIM + ac;  // MODE 0,1 (K-major rows)
    const int bkr = tid >> 5;          // 0..7
    const int bnc = (tid & 31) * 4;    // 0..124
    const float* BptrN = Bin + (size_t)bkr * NDIM + nBase + bnc;  // MODE 2 (N-major rows)

    float acc[TM][TN];
    #pragma unroll
    for (int i = 0; i < TM; i++)
        #pragma unroll
        for (int j = 0; j < TN; j++) acc[i][j] = 0.f;

    float rowsum[TM];
    #pragma unroll
    for (int i = 0; i < TM; i++) rowsum[i] = 0.f;

    // ---- prologue: load tile 0 into buffer 0 ----
    {
        float4 av = *(const float4*)Aptr; Aptr += BK;
        As[0][ac + 0][ar] = av.x;
        As[0][ac + 1][ar] = av.y;
        As[0][ac + 2][ar] = av.z;
        As[0][ac + 3][ar] = av.w;
        if (MODE < 2) {
            float4 bv = *(const float4*)BptrK; BptrK += BK;
            Bs[0][ac + 0][ar] = bv.x;
            Bs[0][ac + 1][ar] = bv.y;
            Bs[0][ac + 2][ar] = bv.z;
            Bs[0][ac + 3][ar] = bv.w;
        } else {
            float4 bv = *(const float4*)BptrN; BptrN += (size_t)BK * NDIM;
            *(float4*)&Bs[0][bkr][bnc] = bv;
        }
    }
    __syncthreads();

    int buf = 0;
    for (int kb = 0; kb < KDIM; kb += BK) {
        const bool more = (kb + BK) < KDIM;

        // ---- prefetch next tile into registers (overlaps with FMA burst) ----
        float4 av2, bv2;
        if (more) {
            av2 = *(const float4*)Aptr; Aptr += BK;
            if (MODE < 2) { bv2 = *(const float4*)BptrK; BptrK += BK; }
            else          { bv2 = *(const float4*)BptrN; BptrN += (size_t)BK * NDIM; }
        }

        // ---- compute from current buffer ----
        #pragma unroll
        for (int k = 0; k < BK; k++) {
            float a[TM], b[TN];
            *(float4*)&a[0] = *(const float4*)&As[buf][k][ty * TM];
            *(float4*)&a[4] = *(const float4*)&As[buf][k][ty * TM + 4];
            *(float4*)&b[0] = *(const float4*)&Bs[buf][k][tx * TN];
            *(float4*)&b[4] = *(const float4*)&Bs[buf][k][tx * TN + 4];
            if (MODE == 2) {
                #pragma unroll
                for (int i = 0; i < TM; i++) rowsum[i] += a[i];
            }
            #pragma unroll
            for (int i = 0; i < TM; i++)
                #pragma unroll
                for (int j = 0; j < TN; j++)
                    acc[i][j] += a[i] * b[j];
        }

        // ---- stage next tile into the other buffer ----
        if (more) {
            const int nb = buf ^ 1;
            As[nb][ac + 0][ar] = av2.x;
            As[nb][ac + 1][ar] = av2.y;
            As[nb][ac + 2][ar] = av2.z;
            As[nb][ac + 3][ar] = av2.w;
            if (MODE < 2) {
                Bs[nb][ac + 0][ar] = bv2.x;
                Bs[nb][ac + 1][ar] = bv2.y;
                Bs[nb][ac + 2][ar] = bv2.z;
                Bs[nb][ac + 3][ar] = bv2.w;
            } else {
                *(float4*)&Bs[nb][bkr][bnc] = bv2;
            }
            __syncthreads();
            buf = nb;
        }
    }

    // ---- epilogue ----
    #pragma unroll
    for (int i = 0; i < TM; i++) {
        const int m = mBase + ty * TM + i;
        float* crow = C + (size_t)m * NDIM + nBase + tx * TN;
        float v[TN];

        if (MODE == 0) {
            const float* brow = bias + nBase + tx * TN;
            #pragma unroll
            for (int j = 0; j < TN; j++) v[j] = acc[i][j] + brow[j];
        } else if (MODE == 1) {
            #pragma unroll
            for (int j = 0; j < TN; j++) {
                float s = acc[i][j];
                float al = 1.f / (1.f + expf(-s));   // sigmoid
                if (al < THRESH) al = 0.f;           // threshold
                v[j] = expf(al);                     // softmax numerator
            }
        } else {
            const float inv = 1.f / rowsum[i];       // softmax denominator (full row)
            #pragma unroll
            for (int j = 0; j < TN; j++) v[j] = acc[i][j] * inv;
        }

        *(float4*)&crow[0] = *(const float4*)&v[0];
        *(float4*)&crow[4] = *(const float4*)&v[4];
    }
}

extern "C" void kernel_launch(void* const* d_in, const int* in_sizes, int n_in,
                              void* d_out, int out_size)
{
    const float* text   = (const float*)d_in[0];  // [8,2048,1024]
    const float* labels = (const float*)d_in[1];  // [4096,768]
    const float* W      = (const float*)d_in[2];  // [768,1024]
    const float* b      = (const float*)d_in[3];  // [768]
    float* out = (float*)d_out;                   // [8,2048,768]

    dim3 blk(256);

    // K1: t = text @ W^T + b  -> g_t
    gemm_k<DT, DL, 0><<<dim3(DL / BN, M_TOTAL / BM), blk>>>(text, W, b, nullptr);

    // K2: w = exp(threshold(sigmoid(t @ labels^T))) -> g_w
    gemm_k<DL, LBL, 1><<<dim3(LBL / BN, M_TOTAL / BM), blk>>>(nullptr, labels, nullptr, nullptr);

    // K3: out = (w @ labels) / rowsum(w)
    gemm_k<LBL, DL, 2><<<dim3(DL / BN, M_TOTAL / BM), blk>>>(nullptr, labels, nullptr, out);
}

// round 5
// speedup vs baseline: 2.3144x; 2.3144x over previous
#include <cuda_runtime.h>
#include <cuda_fp16.h>
#include <cstdint>
#include <math.h>

#define M_TOTAL 16384
#define DT      1024
#define DL      768
#define LBL     4096
#define THRESH  0.4f

// Scratch (no allocations allowed -> __device__ globals)
__device__ float g_t[(size_t)M_TOTAL * DL];    // 48 MB  projected text
__device__ float g_w[(size_t)M_TOTAL * LBL];   // 256 MB softmax numerators
__device__ float g_lt[(size_t)DL * LBL];       // 12 MB  labels transposed [DL][LBL]
__device__ float g_part[(size_t)M_TOTAL * 64]; // 4 MB   per-row partial sums
__device__ float g_inv[M_TOTAL];               // 64 KB  1/rowsum

// m16n8k16 fp16 MMA, fp32 accumulate (baseline PTX, sm_80+)
#define MMA16816(C, Ar, Br) \
    asm volatile("mma.sync.aligned.m16n8k16.row.col.f32.f16.f16.f32 " \
        "{%0,%1,%2,%3}, {%4,%5,%6,%7}, {%8,%9}, {%0,%1,%2,%3};" \
        : "+f"((C)[0]), "+f"((C)[1]), "+f"((C)[2]), "+f"((C)[3]) \
        : "r"((Ar)[0]), "r"((Ar)[1]), "r"((Ar)[2]), "r"((Ar)[3]), \
          "r"((Br)[0]), "r"((Br)[1]))

// ============================ main GEMM kernel ============================
// C[128x128] per CTA, 8 warps (4x2), warp tile 32x64.
// fp32 emulated via 2-way fp16 split: x = h1 + h2 (11+11 mantissa bits);
// 3 fragment products per mma position: h1*g1 + h1*g2 + h2*g1 (err ~2^-22).
// smem: [buf][op][term][128 rows][40 halves] (80B padded rows), double buffered.
// MODE 0: g_t = text @ W^T + bias          (K=1024, N=768)
// MODE 1: g_w = exp(thr(sigm(g_t @ L^T)))  (K=768,  N=4096) + partial rowsums
// MODE 2: out = (g_w @ labels) * g_inv     (K=4096, N=768; B = g_lt)
template<int KDIM, int NDIM, int MODE>
__global__ __launch_bounds__(256, 2)
void gemm_hmma(const float* __restrict__ Ap, const float* __restrict__ Bp,
               const float* __restrict__ bias, float* __restrict__ Cp)
{
    constexpr int NCH    = KDIM / 32;     // K-chunks of 32 fp32
    constexpr int STRIDE = 40;            // halves per smem row (80B, conflict-free)
    constexpr int TSIZE  = 128 * STRIDE;  // halves per term tile

    extern __shared__ __align__(16) __half smh[];

    const float* A = (MODE == 1) ? g_t : (MODE == 2 ? g_w : Ap);
    const float* B = (MODE == 2) ? g_lt : Bp;
    float*       C = (MODE == 0) ? g_t : (MODE == 1 ? g_w : Cp);

    const int tid  = threadIdx.x;
    const int wid  = tid >> 5;
    const int lane = tid & 31;
    const int g    = lane >> 2;     // group 0..7
    const int tig  = lane & 3;      // thread-in-group
    const int wm   = wid & 3;       // warp m index (4)
    const int wn   = wid >> 2;      // warp n index (2)
    const int mrow = wm * 32;
    const int ncol = wn * 64;
    const int mBase = blockIdx.y * 128;
    const int nBase = blockIdx.x * 128;

    const float* Ag = A + (size_t)mBase * KDIM;
    const float* Bg = B + (size_t)nBase * KDIM;

    float acc[2][8][4];
    #pragma unroll
    for (int mt = 0; mt < 2; mt++)
        #pragma unroll
        for (int nt = 0; nt < 8; nt++)
            #pragma unroll
            for (int e = 0; e < 4; e++) acc[mt][nt][e] = 0.f;

    float4 va[4], vb[4];

    // -------- chunk load (fp32 from gmem) --------
    auto LOADCH = [&](int kb) {
        #pragma unroll
        for (int t = 0; t < 4; t++) {
            const int i = tid + t * 256, r = i >> 3, c4 = i & 7;
            va[t] = *(const float4*)(Ag + (size_t)r * KDIM + kb * 32 + c4 * 4);
        }
        #pragma unroll
        for (int t = 0; t < 4; t++) {
            const int i = tid + t * 256, r = i >> 3, c4 = i & 7;
            vb[t] = *(const float4*)(Bg + (size_t)r * KDIM + kb * 32 + c4 * 4);
        }
    };

    // -------- split fp32 -> (h1,h2) fp16 terms and store to smem --------
    auto CVTSTORE = [&](int buf) {
        #pragma unroll
        for (int op = 0; op < 2; op++) {
            const float4* v = op ? vb : va;
            __half* base0 = smh + ((buf * 2 + op) * 2 + 0) * TSIZE;
            __half* base1 = base0 + TSIZE;
            #pragma unroll
            for (int t = 0; t < 4; t++) {
                const int i = tid + t * 256, r = i >> 3, c4 = i & 7;
                const int off = r * STRIDE + c4 * 4;
                float4 x = v[t];
                __half2 h1a = __floats2half2_rn(x.x, x.y);
                __half2 h1b = __floats2half2_rn(x.z, x.w);
                float2 f1 = __half22float2(h1a);
                float2 f2 = __half22float2(h1b);
                __half2 h2a = __floats2half2_rn(x.x - f1.x, x.y - f1.y);
                __half2 h2b = __floats2half2_rn(x.z - f2.x, x.w - f2.y);
                uint2 s1 = make_uint2(*(uint32_t*)&h1a, *(uint32_t*)&h1b);
                uint2 s2 = make_uint2(*(uint32_t*)&h2a, *(uint32_t*)&h2b);
                *(uint2*)(base0 + off) = s1;
                *(uint2*)(base1 + off) = s2;
            }
        }
    };

    auto LDSA = [&](int buf, int term, int m, int k) -> uint32_t {
        return *(const uint32_t*)(smh + ((buf * 2 + 0) * 2 + term) * TSIZE + m * STRIDE + k);
    };
    auto LDSB = [&](int buf, int term, int n, int k) -> uint32_t {
        return *(const uint32_t*)(smh + ((buf * 2 + 1) * 2 + term) * TSIZE + n * STRIDE + k);
    };

    // -------- prologue --------
    LOADCH(0);
    CVTSTORE(0);
    __syncthreads();

    for (int kb = 0; kb < NCH; kb++) {
        const int buf = kb & 1;
        const bool more = (kb + 1) < NCH;
        if (more) LOADCH(kb + 1);

        #pragma unroll
        for (int ks = 0; ks < 32; ks += 16) {
            const int k0 = ks + tig * 2;
            uint32_t A1[2][4], A2[2][4], B1[8][2], B2[8][2];

            #pragma unroll
            for (int mt = 0; mt < 2; mt++) {
                const int m = mrow + mt * 16 + g;
                A1[mt][0] = LDSA(buf, 0, m,     k0);
                A1[mt][1] = LDSA(buf, 0, m + 8, k0);
                A1[mt][2] = LDSA(buf, 0, m,     k0 + 8);
                A1[mt][3] = LDSA(buf, 0, m + 8, k0 + 8);
            }
            #pragma unroll
            for (int nt = 0; nt < 8; nt++) {
                const int n = ncol + nt * 8 + g;
                B1[nt][0] = LDSB(buf, 0, n, k0);
                B1[nt][1] = LDSB(buf, 0, n, k0 + 8);
            }
            // product h1*g1
            #pragma unroll
            for (int mt = 0; mt < 2; mt++)
                #pragma unroll
                for (int nt = 0; nt < 8; nt++) MMA16816(acc[mt][nt], A1[mt], B1[nt]);

            #pragma unroll
            for (int nt = 0; nt < 8; nt++) {
                const int n = ncol + nt * 8 + g;
                B2[nt][0] = LDSB(buf, 1, n, k0);
                B2[nt][1] = LDSB(buf, 1, n, k0 + 8);
            }
            // product h1*g2
            #pragma unroll
            for (int mt = 0; mt < 2; mt++)
                #pragma unroll
                for (int nt = 0; nt < 8; nt++) MMA16816(acc[mt][nt], A1[mt], B2[nt]);

            #pragma unroll
            for (int mt = 0; mt < 2; mt++) {
                const int m = mrow + mt * 16 + g;
                A2[mt][0] = LDSA(buf, 1, m,     k0);
                A2[mt][1] = LDSA(buf, 1, m + 8, k0);
                A2[mt][2] = LDSA(buf, 1, m,     k0 + 8);
                A2[mt][3] = LDSA(buf, 1, m + 8, k0 + 8);
            }
            // product h2*g1
            #pragma unroll
            for (int mt = 0; mt < 2; mt++)
                #pragma unroll
                for (int nt = 0; nt < 8; nt++) MMA16816(acc[mt][nt], A2[mt], B1[nt]);
        }

        if (more) CVTSTORE(buf ^ 1);
        __syncthreads();
    }

    // -------- epilogue --------
    float rs[2][2] = {{0.f, 0.f}, {0.f, 0.f}};   // MODE1 per-thread row partials

    #pragma unroll
    for (int mt = 0; mt < 2; mt++) {
        #pragma unroll
        for (int nt = 0; nt < 8; nt++) {
            const int r0 = mBase + mrow + mt * 16 + g;
            const int r1 = r0 + 8;
            const int c  = nBase + ncol + nt * 8 + tig * 2;
            float v0 = acc[mt][nt][0], v1 = acc[mt][nt][1];
            float v2 = acc[mt][nt][2], v3 = acc[mt][nt][3];

            if (MODE == 0) {
                const float b0 = bias[c], b1 = bias[c + 1];
                v0 += b0; v1 += b1; v2 += b0; v3 += b1;
            } else if (MODE == 1) {
                float a0 = 1.f / (1.f + expf(-v0)); if (a0 < THRESH) a0 = 0.f; v0 = expf(a0);
                float a1 = 1.f / (1.f + expf(-v1)); if (a1 < THRESH) a1 = 0.f; v1 = expf(a1);
                float a2 = 1.f / (1.f + expf(-v2)); if (a2 < THRESH) a2 = 0.f; v2 = expf(a2);
                float a3 = 1.f / (1.f + expf(-v3)); if (a3 < THRESH) a3 = 0.f; v3 = expf(a3);
                rs[mt][0] += v0 + v1;
                rs[mt][1] += v2 + v3;
            } else {
                const float i0 = g_inv[r0], i1 = g_inv[r1];
                v0 *= i0; v1 *= i0; v2 *= i1; v3 *= i1;
            }
            *(float2*)(C + (size_t)r0 * NDIM + c) = make_float2(v0, v1);
            *(float2*)(C + (size_t)r1 * NDIM + c) = make_float2(v2, v3);
        }
    }

    if (MODE == 1) {
        // reduce across the 4 threads of each group (they cover the 8 cols x 8 tiles)
        #pragma unroll
        for (int mt = 0; mt < 2; mt++) {
            #pragma unroll
            for (int h = 0; h < 2; h++) {
                rs[mt][h] += __shfl_xor_sync(0xffffffffu, rs[mt][h], 1);
                rs[mt][h] += __shfl_xor_sync(0xffffffffu, rs[mt][h], 2);
            }
        }
        __syncthreads();                     // smem buffers no longer needed
        float* red = (float*)smh;            // [128 rows][2 warp-cols]
        if (tig == 0) {
            red[(mrow + g)      * 2 + wn] = rs[0][0];
            red[(mrow + g + 8)  * 2 + wn] = rs[0][1];
            red[(mrow + g + 16) * 2 + wn] = rs[1][0];
            red[(mrow + g + 24) * 2 + wn] = rs[1][1];
        }
        __syncthreads();
        if (tid < 128)
            g_part[(size_t)(mBase + tid) * 64 + blockIdx.x] = red[tid * 2] + red[tid * 2 + 1];
    }
}

// ---------------- labels transpose: [LBL][DL] -> g_lt [DL][LBL] ----------------
__global__ void transp_k(const float* __restrict__ in)
{
    __shared__ float t[32][33];
    const int bx = blockIdx.x * 32;   // DL dim
    const int by = blockIdx.y * 32;   // LBL dim
    const int x = threadIdx.x, y = threadIdx.y;
    #pragma unroll
    for (int j = 0; j < 32; j += 8)
        t[y + j][x] = in[(size_t)(by + y + j) * DL + bx + x];
    __syncthreads();
    #pragma unroll
    for (int j = 0; j < 32; j += 8)
        g_lt[(size_t)(bx + y + j) * LBL + by + x] = t[x][y + j];
}

// ---------------- row-sum inverse (deterministic) ----------------
__global__ void rowinv_k()
{
    const int m = blockIdx.x * 256 + threadIdx.x;
    float s = 0.f;
    #pragma unroll
    for (int p = 0; p < 32; p++) s += g_part[(size_t)m * 64 + p];
    g_inv[m] = 1.f / s;
}

// ============================ host launcher ============================
#define SMEM_H (2 * 2 * 2 * 128 * 40 * 2)   // 81920 bytes

extern "C" void kernel_launch(void* const* d_in, const int* in_sizes, int n_in,
                              void* d_out, int out_size)
{
    const float* text   = (const float*)d_in[0];  // [8,2048,1024]
    const float* labels = (const float*)d_in[1];  // [4096,768]
    const float* W      = (const float*)d_in[2];  // [768,1024]
    const float* b      = (const float*)d_in[3];  // [768]
    float* out = (float*)d_out;                   // [8,2048,768]

    cudaFuncSetAttribute(gemm_hmma<DT, DL, 0>,
                         cudaFuncAttributeMaxDynamicSharedMemorySize, SMEM_H);
    cudaFuncSetAttribute(gemm_hmma<DL, LBL, 1>,
                         cudaFuncAttributeMaxDynamicSharedMemorySize, SMEM_H);
    cudaFuncSetAttribute(gemm_hmma<LBL, DL, 2>,
                         cudaFuncAttributeMaxDynamicSharedMemorySize, SMEM_H);

    // labels^T for GEMM3 (K-major B)
    transp_k<<<dim3(DL / 32, LBL / 32), dim3(32, 8)>>>(labels);

    // K1: t = text @ W^T + b
    gemm_hmma<DT, DL, 0><<<dim3(DL / 128, M_TOTAL / 128), 256, SMEM_H>>>(text, W, b, nullptr);

    // K2: w = exp(threshold(sigmoid(t @ labels^T))) + partial rowsums
    gemm_hmma<DL, LBL, 1><<<dim3(LBL / 128, M_TOTAL / 128), 256, SMEM_H>>>(nullptr, labels, nullptr, nullptr);

    // rowsum inverse
    rowinv_k<<<M_TOTAL / 256, 256>>>();

    // K3: out = (w @ labels) / rowsum
    gemm_hmma<LBL, DL, 2><<<dim3(DL / 128, M_TOTAL / 128), 256, SMEM_H>>>(nullptr, nullptr, nullptr, out);
}

// round 6
// speedup vs baseline: 3.3051x; 1.4281x over previous
#include <cuda_runtime.h>
#include <cuda_fp16.h>
#include <cstdint>
#include <math.h>

#define M_TOTAL 16384
#define DT      1024
#define DL      768
#define LBL     4096
#define THRESH  0.4f

// Scratch (no allocations allowed -> __device__ globals)
__device__ float  g_t[(size_t)M_TOTAL * DL];     // 48 MB   projected text
__device__ __half g_wh[(size_t)M_TOTAL * LBL];   // 128 MB  softmax numerators (fp16)
__device__ __half g_lth[(size_t)DL * LBL];       // 6 MB    labels^T fp16 [DL][LBL]
__device__ float  g_part[(size_t)M_TOTAL * 64];  // 4 MB    per-row partial sums
__device__ float  g_inv[M_TOTAL];                // 64 KB   1/rowsum

// m16n8k16 fp16 MMA, fp32 accumulate (baseline PTX, sm_80+)
#define MMA16816(C, Ar, Br) \
    asm volatile("mma.sync.aligned.m16n8k16.row.col.f32.f16.f16.f32 " \
        "{%0,%1,%2,%3}, {%4,%5,%6,%7}, {%8,%9}, {%0,%1,%2,%3};" \
        : "+f"((C)[0]), "+f"((C)[1]), "+f"((C)[2]), "+f"((C)[3]) \
        : "r"((Ar)[0]), "r"((Ar)[1]), "r"((Ar)[2]), "r"((Ar)[3]), \
          "r"((Br)[0]), "r"((Br)[1]))

// ============ GEMM 1/2: fp32 via 2-way fp16 split (3 products) ============
// C[128x128] per CTA, 8 warps (4x2), warp tile 32x64, K-chunks of 32 fp32.
// MODE 0: g_t  = text @ W^T + bias                (K=1024, N=768)
// MODE 1: g_wh = fp16(exp(thr(sigm(g_t @ L^T))))  (K=768,  N=4096) + partial rowsums
template<int KDIM, int NDIM, int MODE>
__global__ __launch_bounds__(256, 2)
void gemm_hmma(const float* __restrict__ Ap, const float* __restrict__ Bp,
               const float* __restrict__ bias, float* __restrict__ Cp)
{
    constexpr int NCH    = KDIM / 32;
    constexpr int STRIDE = 40;            // halves per smem row (80B, conflict-free)
    constexpr int TSIZE  = 128 * STRIDE;

    extern __shared__ __align__(16) __half smh[];

    const float* A = (MODE == 1) ? g_t : Ap;
    const float* B = Bp;
    float*       C = (MODE == 0) ? g_t : Cp;

    const int tid  = threadIdx.x;
    const int wid  = tid >> 5;
    const int lane = tid & 31;
    const int g    = lane >> 2;
    const int tig  = lane & 3;
    const int wm   = wid & 3;
    const int wn   = wid >> 2;
    const int mrow = wm * 32;
    const int ncol = wn * 64;
    const int mBase = blockIdx.y * 128;
    const int nBase = blockIdx.x * 128;

    const float* Ag = A + (size_t)mBase * KDIM;
    const float* Bg = B + (size_t)nBase * KDIM;

    float acc[2][8][4];
    #pragma unroll
    for (int mt = 0; mt < 2; mt++)
        #pragma unroll
        for (int nt = 0; nt < 8; nt++)
            #pragma unroll
            for (int e = 0; e < 4; e++) acc[mt][nt][e] = 0.f;

    float4 va[4], vb[4];

    auto LOADCH = [&](int kb) {
        #pragma unroll
        for (int t = 0; t < 4; t++) {
            const int i = tid + t * 256, r = i >> 3, c4 = i & 7;
            va[t] = *(const float4*)(Ag + (size_t)r * KDIM + kb * 32 + c4 * 4);
        }
        #pragma unroll
        for (int t = 0; t < 4; t++) {
            const int i = tid + t * 256, r = i >> 3, c4 = i & 7;
            vb[t] = *(const float4*)(Bg + (size_t)r * KDIM + kb * 32 + c4 * 4);
        }
    };

    auto CVTSTORE = [&](int buf) {
        #pragma unroll
        for (int op = 0; op < 2; op++) {
            const float4* v = op ? vb : va;
            __half* base0 = smh + ((buf * 2 + op) * 2 + 0) * TSIZE;
            __half* base1 = base0 + TSIZE;
            #pragma unroll
            for (int t = 0; t < 4; t++) {
                const int i = tid + t * 256, r = i >> 3, c4 = i & 7;
                const int off = r * STRIDE + c4 * 4;
                float4 x = v[t];
                __half2 h1a = __floats2half2_rn(x.x, x.y);
                __half2 h1b = __floats2half2_rn(x.z, x.w);
                float2 f1 = __half22float2(h1a);
                float2 f2 = __half22float2(h1b);
                __half2 h2a = __floats2half2_rn(x.x - f1.x, x.y - f1.y);
                __half2 h2b = __floats2half2_rn(x.z - f2.x, x.w - f2.y);
                *(uint2*)(base0 + off) = make_uint2(*(uint32_t*)&h1a, *(uint32_t*)&h1b);
                *(uint2*)(base1 + off) = make_uint2(*(uint32_t*)&h2a, *(uint32_t*)&h2b);
            }
        }
    };

    auto LDSA = [&](int buf, int term, int m, int k) -> uint32_t {
        return *(const uint32_t*)(smh + ((buf * 2 + 0) * 2 + term) * TSIZE + m * STRIDE + k);
    };
    auto LDSB = [&](int buf, int term, int n, int k) -> uint32_t {
        return *(const uint32_t*)(smh + ((buf * 2 + 1) * 2 + term) * TSIZE + n * STRIDE + k);
    };

    LOADCH(0);
    CVTSTORE(0);
    __syncthreads();

    for (int kb = 0; kb < NCH; kb++) {
        const int buf = kb & 1;
        const bool more = (kb + 1) < NCH;
        if (more) LOADCH(kb + 1);

        #pragma unroll
        for (int ks = 0; ks < 32; ks += 16) {
            const int k0 = ks + tig * 2;
            uint32_t A1[2][4], A2[2][4], B1[8][2], B2[8][2];

            #pragma unroll
            for (int mt = 0; mt < 2; mt++) {
                const int m = mrow + mt * 16 + g;
                A1[mt][0] = LDSA(buf, 0, m,     k0);
                A1[mt][1] = LDSA(buf, 0, m + 8, k0);
                A1[mt][2] = LDSA(buf, 0, m,     k0 + 8);
                A1[mt][3] = LDSA(buf, 0, m + 8, k0 + 8);
            }
            #pragma unroll
            for (int nt = 0; nt < 8; nt++) {
                const int n = ncol + nt * 8 + g;
                B1[nt][0] = LDSB(buf, 0, n, k0);
                B1[nt][1] = LDSB(buf, 0, n, k0 + 8);
            }
            #pragma unroll
            for (int mt = 0; mt < 2; mt++)
                #pragma unroll
                for (int nt = 0; nt < 8; nt++) MMA16816(acc[mt][nt], A1[mt], B1[nt]);

            #pragma unroll
            for (int nt = 0; nt < 8; nt++) {
                const int n = ncol + nt * 8 + g;
                B2[nt][0] = LDSB(buf, 1, n, k0);
                B2[nt][1] = LDSB(buf, 1, n, k0 + 8);
            }
            #pragma unroll
            for (int mt = 0; mt < 2; mt++)
                #pragma unroll
                for (int nt = 0; nt < 8; nt++) MMA16816(acc[mt][nt], A1[mt], B2[nt]);

            #pragma unroll
            for (int mt = 0; mt < 2; mt++) {
                const int m = mrow + mt * 16 + g;
                A2[mt][0] = LDSA(buf, 1, m,     k0);
                A2[mt][1] = LDSA(buf, 1, m + 8, k0);
                A2[mt][2] = LDSA(buf, 1, m,     k0 + 8);
                A2[mt][3] = LDSA(buf, 1, m + 8, k0 + 8);
            }
            #pragma unroll
            for (int mt = 0; mt < 2; mt++)
                #pragma unroll
                for (int nt = 0; nt < 8; nt++) MMA16816(acc[mt][nt], A2[mt], B1[nt]);
        }

        if (more) CVTSTORE(buf ^ 1);
        __syncthreads();
    }

    // -------- epilogue --------
    float rs[2][2] = {{0.f, 0.f}, {0.f, 0.f}};

    #pragma unroll
    for (int mt = 0; mt < 2; mt++) {
        #pragma unroll
        for (int nt = 0; nt < 8; nt++) {
            const int r0 = mBase + mrow + mt * 16 + g;
            const int r1 = r0 + 8;
            const int c  = nBase + ncol + nt * 8 + tig * 2;
            float v0 = acc[mt][nt][0], v1 = acc[mt][nt][1];
            float v2 = acc[mt][nt][2], v3 = acc[mt][nt][3];

            if (MODE == 0) {
                const float b0 = bias[c], b1 = bias[c + 1];
                v0 += b0; v1 += b1; v2 += b0; v3 += b1;
                *(float2*)(C + (size_t)r0 * NDIM + c) = make_float2(v0, v1);
                *(float2*)(C + (size_t)r1 * NDIM + c) = make_float2(v2, v3);
            } else {
                float a0 = 1.f / (1.f + expf(-v0)); if (a0 < THRESH) a0 = 0.f; v0 = expf(a0);
                float a1 = 1.f / (1.f + expf(-v1)); if (a1 < THRESH) a1 = 0.f; v1 = expf(a1);
                float a2 = 1.f / (1.f + expf(-v2)); if (a2 < THRESH) a2 = 0.f; v2 = expf(a2);
                float a3 = 1.f / (1.f + expf(-v3)); if (a3 < THRESH) a3 = 0.f; v3 = expf(a3);
                rs[mt][0] += v0 + v1;
                rs[mt][1] += v2 + v3;
                __half2 w0 = __floats2half2_rn(v0, v1);
                __half2 w1 = __floats2half2_rn(v2, v3);
                *(__half2*)(g_wh + (size_t)r0 * NDIM + c) = w0;
                *(__half2*)(g_wh + (size_t)r1 * NDIM + c) = w1;
            }
        }
    }

    if (MODE == 1) {
        #pragma unroll
        for (int mt = 0; mt < 2; mt++)
            #pragma unroll
            for (int h = 0; h < 2; h++) {
                rs[mt][h] += __shfl_xor_sync(0xffffffffu, rs[mt][h], 1);
                rs[mt][h] += __shfl_xor_sync(0xffffffffu, rs[mt][h], 2);
            }
        __syncthreads();
        float* red = (float*)smh;
        if (tig == 0) {
            red[(mrow + g)      * 2 + wn] = rs[0][0];
            red[(mrow + g + 8)  * 2 + wn] = rs[0][1];
            red[(mrow + g + 16) * 2 + wn] = rs[1][0];
            red[(mrow + g + 24) * 2 + wn] = rs[1][1];
        }
        __syncthreads();
        if (tid < 128)
            g_part[(size_t)(mBase + tid) * 64 + blockIdx.x] = red[tid * 2] + red[tid * 2 + 1];
    }
}

// ============ GEMM 3: plain fp16 (1 product) ============
// out[m][n] = (sum_k w[m][k] * labels[k][n]) * g_inv[m]
// A = g_wh [M][4096] fp16, B = g_lth [768][4096] fp16. K-chunks of 64.
__global__ __launch_bounds__(256, 2)
void gemm3_fp16(float* __restrict__ out)
{
    constexpr int KDIM = LBL, NDIM = DL;
    constexpr int NCH = KDIM / 64;
    constexpr int STRIDE = 72;            // halves per row (144B, conflict-free)
    constexpr int TSIZE  = 128 * STRIDE;

    extern __shared__ __align__(16) __half smh[];

    const int tid  = threadIdx.x;
    const int wid  = tid >> 5;
    const int lane = tid & 31;
    const int g    = lane >> 2;
    const int tig  = lane & 3;
    const int wm   = wid & 3;
    const int wn   = wid >> 2;
    const int mrow = wm * 32;
    const int ncol = wn * 64;
    const int mBase = blockIdx.y * 128;
    const int nBase = blockIdx.x * 128;

    const __half* Ag = g_wh + (size_t)mBase * KDIM;
    const __half* Bg = g_lth + (size_t)nBase * KDIM;

    float acc[2][8][4];
    #pragma unroll
    for (int mt = 0; mt < 2; mt++)
        #pragma unroll
        for (int nt = 0; nt < 8; nt++)
            #pragma unroll
            for (int e = 0; e < 4; e++) acc[mt][nt][e] = 0.f;

    uint4 ua[4], ub[4];

    auto LOADCH = [&](int kb) {
        #pragma unroll
        for (int t = 0; t < 4; t++) {
            const int i = tid + t * 256, r = i >> 3, c8 = (i & 7) * 8;
            ua[t] = *(const uint4*)(Ag + (size_t)r * KDIM + kb * 64 + c8);
        }
        #pragma unroll
        for (int t = 0; t < 4; t++) {
            const int i = tid + t * 256, r = i >> 3, c8 = (i & 7) * 8;
            ub[t] = *(const uint4*)(Bg + (size_t)r * KDIM + kb * 64 + c8);
        }
    };

    auto STORECH = [&](int buf) {
        __half* ba = smh + (buf * 2 + 0) * TSIZE;
        __half* bb = smh + (buf * 2 + 1) * TSIZE;
        #pragma unroll
        for (int t = 0; t < 4; t++) {
            const int i = tid + t * 256, r = i >> 3, c8 = (i & 7) * 8;
            *(uint4*)(ba + r * STRIDE + c8) = ua[t];
        }
        #pragma unroll
        for (int t = 0; t < 4; t++) {
            const int i = tid + t * 256, r = i >> 3, c8 = (i & 7) * 8;
            *(uint4*)(bb + r * STRIDE + c8) = ub[t];
        }
    };

    auto LDSA = [&](int buf, int m, int k) -> uint32_t {
        return *(const uint32_t*)(smh + (buf * 2 + 0) * TSIZE + m * STRIDE + k);
    };
    auto LDSB = [&](int buf, int n, int k) -> uint32_t {
        return *(const uint32_t*)(smh + (buf * 2 + 1) * TSIZE + n * STRIDE + k);
    };

    LOADCH(0);
    STORECH(0);
    __syncthreads();

    for (int kb = 0; kb < NCH; kb++) {
        const int buf = kb & 1;
        const bool more = (kb + 1) < NCH;
        if (more) LOADCH(kb + 1);

        #pragma unroll
        for (int ks = 0; ks < 64; ks += 16) {
            const int k0 = ks + tig * 2;
            uint32_t Af[2][4], Bf[8][2];
            #pragma unroll
            for (int mt = 0; mt < 2; mt++) {
                const int m = mrow + mt * 16 + g;
                Af[mt][0] = LDSA(buf, m,     k0);
                Af[mt][1] = LDSA(buf, m + 8, k0);
                Af[mt][2] = LDSA(buf, m,     k0 + 8);
                Af[mt][3] = LDSA(buf, m + 8, k0 + 8);
            }
            #pragma unroll
            for (int nt = 0; nt < 8; nt++) {
                const int n = ncol + nt * 8 + g;
                Bf[nt][0] = LDSB(buf, n, k0);
                Bf[nt][1] = LDSB(buf, n, k0 + 8);
            }
            #pragma unroll
            for (int mt = 0; mt < 2; mt++)
                #pragma unroll
                for (int nt = 0; nt < 8; nt++) MMA16816(acc[mt][nt], Af[mt], Bf[nt]);
        }

        if (more) STORECH(buf ^ 1);
        __syncthreads();
    }

    // -------- epilogue --------
    #pragma unroll
    for (int mt = 0; mt < 2; mt++) {
        #pragma unroll
        for (int nt = 0; nt < 8; nt++) {
            const int r0 = mBase + mrow + mt * 16 + g;
            const int r1 = r0 + 8;
            const int c  = nBase + ncol + nt * 8 + tig * 2;
            const float i0 = g_inv[r0], i1 = g_inv[r1];
            *(float2*)(out + (size_t)r0 * NDIM + c) =
                make_float2(acc[mt][nt][0] * i0, acc[mt][nt][1] * i0);
            *(float2*)(out + (size_t)r1 * NDIM + c) =
                make_float2(acc[mt][nt][2] * i1, acc[mt][nt][3] * i1);
        }
    }
}

// ---------------- labels transpose: [LBL][DL] fp32 -> g_lth [DL][LBL] fp16 ----------------
__global__ void transp_k(const float* __restrict__ in)
{
    __shared__ float t[32][33];
    const int bx = blockIdx.x * 32;   // DL dim
    const int by = blockIdx.y * 32;   // LBL dim
    const int x = threadIdx.x, y = threadIdx.y;
    #pragma unroll
    for (int j = 0; j < 32; j += 8)
        t[y + j][x] = in[(size_t)(by + y + j) * DL + bx + x];
    __syncthreads();
    #pragma unroll
    for (int j = 0; j < 32; j += 8)
        g_lth[(size_t)(bx + y + j) * LBL + by + x] = __float2half_rn(t[x][y + j]);
}

// ---------------- row-sum inverse (deterministic) ----------------
__global__ void rowinv_k()
{
    const int m = blockIdx.x * 256 + threadIdx.x;
    float s = 0.f;
    #pragma unroll
    for (int p = 0; p < 32; p++) s += g_part[(size_t)m * 64 + p];
    g_inv[m] = 1.f / s;
}

// ============================ host launcher ============================
#define SMEM_H  (2 * 2 * 2 * 128 * 40 * 2)   // 81920 bytes  (split GEMMs)
#define SMEM_G3 (2 * 2 * 128 * 72 * 2)       // 73728 bytes  (fp16 GEMM3)

extern "C" void kernel_launch(void* const* d_in, const int* in_sizes, int n_in,
                              void* d_out, int out_size)
{
    const float* text   = (const float*)d_in[0];  // [8,2048,1024]
    const float* labels = (const float*)d_in[1];  // [4096,768]
    const float* W      = (const float*)d_in[2];  // [768,1024]
    const float* b      = (const float*)d_in[3];  // [768]
    float* out = (float*)d_out;                   // [8,2048,768]

    cudaFuncSetAttribute(gemm_hmma<DT, DL, 0>,
                         cudaFuncAttributeMaxDynamicSharedMemorySize, SMEM_H);
    cudaFuncSetAttribute(gemm_hmma<DL, LBL, 1>,
                         cudaFuncAttributeMaxDynamicSharedMemorySize, SMEM_H);
    cudaFuncSetAttribute(gemm3_fp16,
                         cudaFuncAttributeMaxDynamicSharedMemorySize, SMEM_G3);

    // labels^T (fp16) for GEMM3
    transp_k<<<dim3(DL / 32, LBL / 32), dim3(32, 8)>>>(labels);

    // K1: t = text @ W^T + b   (3-product split)
    gemm_hmma<DT, DL, 0><<<dim3(DL / 128, M_TOTAL / 128), 256, SMEM_H>>>(text, W, b, nullptr);

    // K2: w = exp(threshold(sigmoid(t @ labels^T)))  -> fp16 + partial rowsums
    gemm_hmma<DL, LBL, 1><<<dim3(LBL / 128, M_TOTAL / 128), 256, SMEM_H>>>(nullptr, labels, nullptr, nullptr);

    // rowsum inverse
    rowinv_k<<<M_TOTAL / 256, 256>>>();

    // K3: out = (w @ labels) / rowsum   (plain fp16)
    gemm3_fp16<<<dim3(DL / 128, M_TOTAL / 128), 256, SMEM_G3>>>(out);
}

// round 7
// speedup vs baseline: 3.8555x; 1.1665x over previous
#include <cuda_runtime.h>
#include <cuda_fp16.h>
#include <cstdint>
#include <math.h>

#define M_TOTAL 16384
#define DT      1024
#define DL      768
#define LBL     4096
#define THRESH  0.4f

// ---------------- scratch (__device__ globals; no allocations allowed) ----------------
__device__ __half g_xh1[(size_t)M_TOTAL * DT];   // text split hi
__device__ __half g_xh2[(size_t)M_TOTAL * DT];   // text split lo
__device__ __half g_Wh1[(size_t)DL * DT];        // W split hi
__device__ __half g_Wh2[(size_t)DL * DT];        // W split lo
__device__ __half g_th1[(size_t)M_TOTAL * DL];   // t split hi
__device__ __half g_th2[(size_t)M_TOTAL * DL];   // t split lo
__device__ __half g_lbh1[(size_t)LBL * DL];      // labels split hi  [L][DL]
__device__ __half g_lbh2[(size_t)LBL * DL];      // labels split lo
__device__ __half g_wh[(size_t)M_TOTAL * LBL];   // softmax numerators fp16
__device__ __half g_lth[(size_t)DL * LBL];       // labels^T fp16 [DL][LBL]
__device__ float  g_part[(size_t)M_TOTAL * 64];  // per-row partial sums
__device__ float  g_inv[M_TOTAL];                // 1/rowsum

// ---------------- PTX helpers ----------------
#define MMA16816(C, Ar, Br) \
    asm volatile("mma.sync.aligned.m16n8k16.row.col.f32.f16.f16.f32 " \
        "{%0,%1,%2,%3}, {%4,%5,%6,%7}, {%8,%9}, {%0,%1,%2,%3};" \
        : "+f"((C)[0]), "+f"((C)[1]), "+f"((C)[2]), "+f"((C)[3]) \
        : "r"((Ar)[0]), "r"((Ar)[1]), "r"((Ar)[2]), "r"((Ar)[3]), \
          "r"((Br)[0]), "r"((Br)[1]))

#define LDSM4(R0, R1, R2, R3, ADDR) \
    asm volatile("ldmatrix.sync.aligned.m8n8.x4.shared.b16 {%0,%1,%2,%3}, [%4];" \
        : "=r"(R0), "=r"(R1), "=r"(R2), "=r"(R3) : "r"(ADDR))

#define CPASYNC16(SMEM, GMEM) \
    asm volatile("cp.async.cg.shared.global [%0], [%1], 16;" \
        :: "r"(SMEM), "l"(GMEM))
#define CPCOMMIT() asm volatile("cp.async.commit_group;" ::: "memory")
#define CPWAIT(N)  asm volatile("cp.async.wait_group %0;" :: "n"(N) : "memory")

__device__ __forceinline__ uint32_t smem_u32(const void* p) {
    uint32_t a;
    asm("{ .reg .u64 t; cvta.to.shared.u64 t, %1; cvt.u32.u64 %0, t; }" : "=r"(a) : "l"(p));
    return a;
}

// ============================ unified HMMA GEMM ============================
// C[128x128] per CTA, 8 warps (4x2), warp tile 32x64.
// Operands are PRE-SPLIT fp16 in gmem. Mainloop: cp.async -> ldmatrix.x4 -> mma.
// NPROD=3: acc = A1*B1 + A1*B2 + A2*B1 (fp32-grade);  NPROD=1: acc = A1*B1.
// MODE 0: t = acc + bias -> split-store (g_th1,g_th2)      [GEMM1]
// MODE 1: w = exp(thr(sigm(acc))) -> g_wh fp16 + partials  [GEMM2]
// MODE 2: out = acc * g_inv[m] -> fp32                     [GEMM3]
template<int KDIM, int NDIM, int KT, int NPROD, int MODE>
__global__ __launch_bounds__(256, 2)
void gemm_async(const __half* __restrict__ A1p, const __half* __restrict__ A2p,
                const __half* __restrict__ B1p, const __half* __restrict__ B2p,
                const float* __restrict__ bias, float* __restrict__ outp)
{
    constexpr int NCH    = KDIM / KT;
    constexpr int STRIDE = KT + 8;            // halves per smem row (pad 16B)
    constexpr int TSIZE  = 128 * STRIDE;      // halves per tile
    constexpr int NT     = (NPROD == 3) ? 4 : 2;   // tiles: A1[,A2],B1[,B2]
    constexpr int TB1    = (NPROD == 3) ? 2 : 1;
    constexpr int CPT    = KT / 8;            // 16B segs per row
    constexpr int PERTHR = (128 * CPT) / 256; // cp.async per thread per tile

    extern __shared__ __align__(16) __half smh[];
    const uint32_t smb = smem_u32(smh);

    const int tid  = threadIdx.x;
    const int wid  = tid >> 5;
    const int lane = tid & 31;
    const int g    = lane >> 2;
    const int tig  = lane & 3;
    const int wm   = wid & 3;
    const int wn   = wid >> 2;
    const int mrow = wm * 32;
    const int ncol = wn * 64;
    const int mBase = blockIdx.y * 128;
    const int nBase = blockIdx.x * 128;

    const __half* Tg[4];
    Tg[0] = A1p + (size_t)mBase * KDIM;
    if (NPROD == 3) {
        Tg[1] = A2p + (size_t)mBase * KDIM;
        Tg[2] = B1p + (size_t)nBase * KDIM;
        Tg[3] = B2p + (size_t)nBase * KDIM;
    } else {
        Tg[1] = B1p + (size_t)nBase * KDIM;
    }

    // ldmatrix per-lane base offsets (halves)
    const int a_off = (mrow + (lane & 7) + ((lane >> 3) & 1) * 8) * STRIDE + ((lane >> 4) & 1) * 8;
    const int b_off = (ncol + (lane & 7) + ((lane >> 4) & 1) * 8) * STRIDE + ((lane >> 3) & 1) * 8;

    float acc[2][8][4];
    #pragma unroll
    for (int mt = 0; mt < 2; mt++)
        #pragma unroll
        for (int nt = 0; nt < 8; nt++)
            #pragma unroll
            for (int e = 0; e < 4; e++) acc[mt][nt][e] = 0.f;

    auto ISSUE = [&](int kb, int buf) {
        #pragma unroll
        for (int tl = 0; tl < NT; tl++) {
            #pragma unroll
            for (int t = 0; t < PERTHR; t++) {
                const int idx = tid + t * 256;
                const int r = idx / CPT, c16 = idx % CPT;
                const uint32_t sa = smb + ((buf * NT + tl) * TSIZE + r * STRIDE) * 2 + c16 * 16;
                const __half* ga = Tg[tl] + (size_t)r * KDIM + kb * KT + c16 * 8;
                CPASYNC16(sa, ga);
            }
        }
        CPCOMMIT();
    };

    ISSUE(0, 0);

    for (int kb = 0; kb < NCH; kb++) {
        const int buf = kb & 1;
        const bool more = (kb + 1) < NCH;
        if (more) { ISSUE(kb + 1, buf ^ 1); CPWAIT(1); }
        else      { CPWAIT(0); }
        __syncthreads();

        const uint32_t tA1 = smb + ((buf * NT + 0) * TSIZE) * 2;
        const uint32_t tA2 = smb + ((buf * NT + 1) * TSIZE) * 2;
        const uint32_t tB1 = smb + ((buf * NT + TB1) * TSIZE) * 2;
        const uint32_t tB2 = smb + ((buf * NT + 3) * TSIZE) * 2;

        #pragma unroll
        for (int ks = 0; ks < KT; ks += 16) {
            uint32_t Af1[2][4], Af2[2][4];
            // A1 fragments (2 x ldmatrix.x4 covering 32 rows x 16 k)
            #pragma unroll
            for (int mt = 0; mt < 2; mt++)
                LDSM4(Af1[mt][0], Af1[mt][1], Af1[mt][2], Af1[mt][3],
                      tA1 + (a_off + mt * 16 * STRIDE + ks) * 2);
            if (NPROD == 3) {
                #pragma unroll
                for (int mt = 0; mt < 2; mt++)
                    LDSM4(Af2[mt][0], Af2[mt][1], Af2[mt][2], Af2[mt][3],
                          tA2 + (a_off + mt * 16 * STRIDE + ks) * 2);
            }
            // B in pairs of two n-tiles (1 ldmatrix.x4 each)
            #pragma unroll
            for (int p = 0; p < 4; p++) {
                uint32_t Bf[4];
                LDSM4(Bf[0], Bf[1], Bf[2], Bf[3],
                      tB1 + (b_off + p * 16 * STRIDE + ks) * 2);
                #pragma unroll
                for (int mt = 0; mt < 2; mt++) {
                    MMA16816(acc[mt][p * 2 + 0], Af1[mt], &Bf[0]);
                    MMA16816(acc[mt][p * 2 + 1], Af1[mt], &Bf[2]);
                }
                if (NPROD == 3) {
                    #pragma unroll
                    for (int mt = 0; mt < 2; mt++) {
                        MMA16816(acc[mt][p * 2 + 0], Af2[mt], &Bf[0]);
                        MMA16816(acc[mt][p * 2 + 1], Af2[mt], &Bf[2]);
                    }
                    uint32_t Bg2[4];
                    LDSM4(Bg2[0], Bg2[1], Bg2[2], Bg2[3],
                          tB2 + (b_off + p * 16 * STRIDE + ks) * 2);
                    #pragma unroll
                    for (int mt = 0; mt < 2; mt++) {
                        MMA16816(acc[mt][p * 2 + 0], Af1[mt], &Bg2[0]);
                        MMA16816(acc[mt][p * 2 + 1], Af1[mt], &Bg2[2]);
                    }
                }
            }
        }
        __syncthreads();
    }

    // ---------------- epilogue ----------------
    float rs[2][2] = {{0.f, 0.f}, {0.f, 0.f}};

    #pragma unroll
    for (int mt = 0; mt < 2; mt++) {
        #pragma unroll
        for (int nt = 0; nt < 8; nt++) {
            const int r0 = mBase + mrow + mt * 16 + g;
            const int r1 = r0 + 8;
            const int c  = nBase + ncol + nt * 8 + tig * 2;
            float v0 = acc[mt][nt][0], v1 = acc[mt][nt][1];
            float v2 = acc[mt][nt][2], v3 = acc[mt][nt][3];

            if (MODE == 0) {
                const float b0 = bias[c], b1 = bias[c + 1];
                v0 += b0; v1 += b1; v2 += b0; v3 += b1;
                __half2 h0 = __floats2half2_rn(v0, v1);
                __half2 h1 = __floats2half2_rn(v2, v3);
                float2 f0 = __half22float2(h0), f1 = __half22float2(h1);
                __half2 l0 = __floats2half2_rn(v0 - f0.x, v1 - f0.y);
                __half2 l1 = __floats2half2_rn(v2 - f1.x, v3 - f1.y);
                *(__half2*)(g_th1 + (size_t)r0 * NDIM + c) = h0;
                *(__half2*)(g_th1 + (size_t)r1 * NDIM + c) = h1;
                *(__half2*)(g_th2 + (size_t)r0 * NDIM + c) = l0;
                *(__half2*)(g_th2 + (size_t)r1 * NDIM + c) = l1;
            } else if (MODE == 1) {
                float a0 = 1.f / (1.f + expf(-v0)); if (a0 < THRESH) a0 = 0.f; v0 = expf(a0);
                float a1 = 1.f / (1.f + expf(-v1)); if (a1 < THRESH) a1 = 0.f; v1 = expf(a1);
                float a2 = 1.f / (1.f + expf(-v2)); if (a2 < THRESH) a2 = 0.f; v2 = expf(a2);
                float a3 = 1.f / (1.f + expf(-v3)); if (a3 < THRESH) a3 = 0.f; v3 = expf(a3);
                rs[mt][0] += v0 + v1;
                rs[mt][1] += v2 + v3;
                *(__half2*)(g_wh + (size_t)r0 * NDIM + c) = __floats2half2_rn(v0, v1);
                *(__half2*)(g_wh + (size_t)r1 * NDIM + c) = __floats2half2_rn(v2, v3);
            } else {
                const float i0 = g_inv[r0], i1 = g_inv[r1];
                *(float2*)(outp + (size_t)r0 * NDIM + c) = make_float2(v0 * i0, v1 * i0);
                *(float2*)(outp + (size_t)r1 * NDIM + c) = make_float2(v2 * i1, v3 * i1);
            }
        }
    }

    if (MODE == 1) {
        #pragma unroll
        for (int mt = 0; mt < 2; mt++)
            #pragma unroll
            for (int h = 0; h < 2; h++) {
                rs[mt][h] += __shfl_xor_sync(0xffffffffu, rs[mt][h], 1);
                rs[mt][h] += __shfl_xor_sync(0xffffffffu, rs[mt][h], 2);
            }
        __syncthreads();
        float* red = (float*)smh;
        if (tig == 0) {
            red[(mrow + g)      * 2 + wn] = rs[0][0];
            red[(mrow + g + 8)  * 2 + wn] = rs[0][1];
            red[(mrow + g + 16) * 2 + wn] = rs[1][0];
            red[(mrow + g + 24) * 2 + wn] = rs[1][1];
        }
        __syncthreads();
        if (tid < 128)
            g_part[(size_t)(mBase + tid) * 64 + blockIdx.x] = red[tid * 2] + red[tid * 2 + 1];
    }
}

// ---------------- elementwise fp32 -> (h1,h2) split ----------------
__global__ void split_k(const float* __restrict__ src,
                        __half* __restrict__ d1, __half* __restrict__ d2, int n4)
{
    const int i = blockIdx.x * 256 + threadIdx.x;
    if (i >= n4) return;
    float4 x = ((const float4*)src)[i];
    __half2 h0 = __floats2half2_rn(x.x, x.y);
    __half2 h1 = __floats2half2_rn(x.z, x.w);
    float2 f0 = __half22float2(h0), f1 = __half22float2(h1);
    __half2 l0 = __floats2half2_rn(x.x - f0.x, x.y - f0.y);
    __half2 l1 = __floats2half2_rn(x.z - f1.x, x.w - f1.y);
    ((uint2*)d1)[i] = make_uint2(*(uint32_t*)&h0, *(uint32_t*)&h1);
    ((uint2*)d2)[i] = make_uint2(*(uint32_t*)&l0, *(uint32_t*)&l1);
}

// ---------------- labels transpose: [LBL][DL] fp32 -> g_lth [DL][LBL] fp16 ----------------
__global__ void transp_k(const float* __restrict__ in)
{
    __shared__ float t[32][33];
    const int bx = blockIdx.x * 32;   // DL dim
    const int by = blockIdx.y * 32;   // LBL dim
    const int x = threadIdx.x, y = threadIdx.y;
    #pragma unroll
    for (int j = 0; j < 32; j += 8)
        t[y + j][x] = in[(size_t)(by + y + j) * DL + bx + x];
    __syncthreads();
    #pragma unroll
    for (int j = 0; j < 32; j += 8)
        g_lth[(size_t)(bx + y + j) * LBL + by + x] = __float2half_rn(t[x][y + j]);
}

// ---------------- row-sum inverse (deterministic) ----------------
__global__ void rowinv_k()
{
    const int m = blockIdx.x * 256 + threadIdx.x;
    float s = 0.f;
    #pragma unroll
    for (int p = 0; p < 32; p++) s += g_part[(size_t)m * 64 + p];
    g_inv[m] = 1.f / s;
}

// ============================ host launcher ============================
#define SMEM_P3 (2 * 4 * 128 * 40 * 2)   // 81920 B  (NPROD=3, KT=32)
#define SMEM_P1 (2 * 2 * 128 * 72 * 2)   // 73728 B  (NPROD=1, KT=64)

extern "C" void kernel_launch(void* const* d_in, const int* in_sizes, int n_in,
                              void* d_out, int out_size)
{
    const float* text   = (const float*)d_in[0];  // [8,2048,1024]
    const float* labels = (const float*)d_in[1];  // [4096,768]
    const float* W      = (const float*)d_in[2];  // [768,1024]
    const float* b      = (const float*)d_in[3];  // [768]
    float* out = (float*)d_out;                   // [8,2048,768]

    __half *xh1, *xh2, *Wh1, *Wh2, *th1, *th2, *lbh1, *lbh2, *wh, *lth;
    cudaGetSymbolAddress((void**)&xh1,  g_xh1);
    cudaGetSymbolAddress((void**)&xh2,  g_xh2);
    cudaGetSymbolAddress((void**)&Wh1,  g_Wh1);
    cudaGetSymbolAddress((void**)&Wh2,  g_Wh2);
    cudaGetSymbolAddress((void**)&th1,  g_th1);
    cudaGetSymbolAddress((void**)&th2,  g_th2);
    cudaGetSymbolAddress((void**)&lbh1, g_lbh1);
    cudaGetSymbolAddress((void**)&lbh2, g_lbh2);
    cudaGetSymbolAddress((void**)&wh,   g_wh);
    cudaGetSymbolAddress((void**)&lth,  g_lth);

    cudaFuncSetAttribute(gemm_async<DT, DL, 32, 3, 0>,
                         cudaFuncAttributeMaxDynamicSharedMemorySize, SMEM_P3);
    cudaFuncSetAttribute(gemm_async<DL, LBL, 32, 3, 1>,
                         cudaFuncAttributeMaxDynamicSharedMemorySize, SMEM_P3);
    cudaFuncSetAttribute(gemm_async<LBL, DL, 64, 1, 2>,
                         cudaFuncAttributeMaxDynamicSharedMemorySize, SMEM_P1);

    // pre-split inputs to fp16 term pairs
    split_k<<<(M_TOTAL * DT / 4 + 255) / 256, 256>>>(text, xh1, xh2, M_TOTAL * DT / 4);
    split_k<<<(DL * DT / 4 + 255) / 256, 256>>>(W, Wh1, Wh2, DL * DT / 4);
    split_k<<<(LBL * DL / 4 + 255) / 256, 256>>>(labels, lbh1, lbh2, LBL * DL / 4);
    transp_k<<<dim3(DL / 32, LBL / 32), dim3(32, 8)>>>(labels);

    // K1: t = text @ W^T + b  (3-product) -> split-stored t
    gemm_async<DT, DL, 32, 3, 0><<<dim3(DL / 128, M_TOTAL / 128), 256, SMEM_P3>>>(
        xh1, xh2, Wh1, Wh2, b, nullptr);

    // K2: w = exp(threshold(sigmoid(t @ labels^T)))  (3-product) -> fp16 + partials
    gemm_async<DL, LBL, 32, 3, 1><<<dim3(LBL / 128, M_TOTAL / 128), 256, SMEM_P3>>>(
        th1, th2, lbh1, lbh2, nullptr, nullptr);

    rowinv_k<<<M_TOTAL / 256, 256>>>();

    // K3: out = (w @ labels) / rowsum  (1-product fp16)
    gemm_async<LBL, DL, 64, 1, 2><<<dim3(DL / 128, M_TOTAL / 128), 256, SMEM_P1>>>(
        wh, nullptr, lth, nullptr, nullptr, out);
}

// round 9
// speedup vs baseline: 3.9177x; 1.0161x over previous
#include <cuda_runtime.h>
#include <cuda_fp16.h>
#include <cstdint>
#include <math.h>

#define M_TOTAL 16384
#define DT      1024
#define DL      768
#define LBL     4096
#define THRESH  0.4f

// ---------------- scratch (__device__ globals; no allocations allowed) ----------------
__device__ __half g_xh1[(size_t)M_TOTAL * DT];   // text split hi
__device__ __half g_xh2[(size_t)M_TOTAL * DT];   // text split lo
__device__ __half g_Wh1[(size_t)DL * DT];        // W split hi
__device__ __half g_Wh2[(size_t)DL * DT];        // W split lo
__device__ __half g_th1[(size_t)M_TOTAL * DL];   // t split hi
__device__ __half g_th2[(size_t)M_TOTAL * DL];   // t split lo
__device__ __half g_lbh1[(size_t)LBL * DL];      // labels split hi  [L][DL]
__device__ __half g_lbh2[(size_t)LBL * DL];      // labels split lo
__device__ __half g_wh[(size_t)M_TOTAL * LBL];   // softmax numerators fp16
__device__ __half g_lth[(size_t)DL * LBL];       // labels^T fp16 [DL][LBL]
__device__ float  g_part[(size_t)M_TOTAL * 64];  // per-row partial sums
__device__ float  g_inv[M_TOTAL];                // 1/rowsum

// ---------------- PTX helpers ----------------
#define MMA16816(C, Ar, Br) \
    asm volatile("mma.sync.aligned.m16n8k16.row.col.f32.f16.f16.f32 " \
        "{%0,%1,%2,%3}, {%4,%5,%6,%7}, {%8,%9}, {%0,%1,%2,%3};" \
        : "+f"((C)[0]), "+f"((C)[1]), "+f"((C)[2]), "+f"((C)[3]) \
        : "r"((Ar)[0]), "r"((Ar)[1]), "r"((Ar)[2]), "r"((Ar)[3]), \
          "r"((Br)[0]), "r"((Br)[1]))

#define LDSM4(R0, R1, R2, R3, ADDR) \
    asm volatile("ldmatrix.sync.aligned.m8n8.x4.shared.b16 {%0,%1,%2,%3}, [%4];" \
        : "=r"(R0), "=r"(R1), "=r"(R2), "=r"(R3) : "r"(ADDR))

#define CPASYNC16(SMEM, GMEM) \
    asm volatile("cp.async.cg.shared.global [%0], [%1], 16;" \
        :: "r"(SMEM), "l"(GMEM))
#define CPCOMMIT() asm volatile("cp.async.commit_group;" ::: "memory")
#define CPWAIT(N)  asm volatile("cp.async.wait_group %0;" :: "n"(N) : "memory")

__device__ __forceinline__ uint32_t smem_u32(const void* p) {
    uint32_t a;
    asm("{ .reg .u64 t; cvta.to.shared.u64 t, %1; cvt.u32.u64 %0, t; }" : "=r"(a) : "l"(p));
    return a;
}

// ============================ unified HMMA GEMM ============================
// C[128x128] per CTA, 8 warps (4x2), warp tile 32x64.
// Operands are PRE-SPLIT fp16 in gmem. Mainloop: cp.async -> batched ldmatrix.x4 -> mma.
// NPROD=3: acc = A1*B1 + A2*B1 + A1*B2;  NPROD=1: acc = A1*B1.
// MODE 0: t = acc + bias -> split-store (g_th1,g_th2)      [GEMM1]
// MODE 1: w = exp(thr(sigm(acc))) -> g_wh fp16 + partials  [GEMM2]
// MODE 2: out = acc * g_inv[m] -> fp32                     [GEMM3]
template<int KDIM, int NDIM, int KT, int NPROD, int MODE>
__global__ __launch_bounds__(256, 2)
void gemm_async(const __half* __restrict__ A1p, const __half* __restrict__ A2p,
                const __half* __restrict__ B1p, const __half* __restrict__ B2p,
                const float* __restrict__ bias, float* __restrict__ outp)
{
    constexpr int NCH    = KDIM / KT;
    constexpr int STRIDE = KT + 8;            // halves per smem row (pad 16B)
    constexpr int TSIZE  = 128 * STRIDE;      // halves per tile
    constexpr int NT     = (NPROD == 3) ? 4 : 2;   // tiles: A1[,A2],B1[,B2]
    constexpr int TB1    = (NPROD == 3) ? 2 : 1;
    constexpr int CPT    = KT / 8;            // 16B segs per row
    constexpr int PERTHR = (128 * CPT) / 256; // cp.async per thread per tile

    extern __shared__ __align__(16) __half smh[];
    const uint32_t smb = smem_u32(smh);

    const int tid  = threadIdx.x;
    const int wid  = tid >> 5;
    const int lane = tid & 31;
    const int g    = lane >> 2;
    const int tig  = lane & 3;
    const int wm   = wid & 3;
    const int wn   = wid >> 2;
    const int mrow = wm * 32;
    const int ncol = wn * 64;
    const int mBase = blockIdx.y * 128;
    const int nBase = blockIdx.x * 128;

    const __half* Tg[4];
    Tg[0] = A1p + (size_t)mBase * KDIM;
    if (NPROD == 3) {
        Tg[1] = A2p + (size_t)mBase * KDIM;
        Tg[2] = B1p + (size_t)nBase * KDIM;
        Tg[3] = B2p + (size_t)nBase * KDIM;
    } else {
        Tg[1] = B1p + (size_t)nBase * KDIM;
    }

    // ldmatrix per-lane base offsets (halves)
    const int a_off = (mrow + (lane & 7) + ((lane >> 3) & 1) * 8) * STRIDE + ((lane >> 4) & 1) * 8;
    const int b_off = (ncol + (lane & 7) + ((lane >> 4) & 1) * 8) * STRIDE + ((lane >> 3) & 1) * 8;

    float acc[2][8][4];
    #pragma unroll
    for (int mt = 0; mt < 2; mt++)
        #pragma unroll
        for (int nt = 0; nt < 8; nt++)
            #pragma unroll
            for (int e = 0; e < 4; e++) acc[mt][nt][e] = 0.f;

    auto ISSUE = [&](int kb, int buf) {
        #pragma unroll
        for (int tl = 0; tl < NT; tl++) {
            #pragma unroll
            for (int t = 0; t < PERTHR; t++) {
                const int idx = tid + t * 256;
                const int r = idx / CPT, c16 = idx % CPT;
                const uint32_t sa = smb + ((buf * NT + tl) * TSIZE + r * STRIDE) * 2 + c16 * 16;
                const __half* ga = Tg[tl] + (size_t)r * KDIM + kb * KT + c16 * 8;
                CPASYNC16(sa, ga);
            }
        }
        CPCOMMIT();
    };

    ISSUE(0, 0);

    for (int kb = 0; kb < NCH; kb++) {
        const int buf = kb & 1;
        const bool more = (kb + 1) < NCH;
        if (more) { ISSUE(kb + 1, buf ^ 1); CPWAIT(1); }
        else      { CPWAIT(0); }
        __syncthreads();

        const uint32_t tA1 = smb + ((buf * NT + 0) * TSIZE) * 2;
        const uint32_t tA2 = smb + ((buf * NT + 1) * TSIZE) * 2;
        const uint32_t tB1 = smb + ((buf * NT + TB1) * TSIZE) * 2;
        const uint32_t tB2 = smb + ((buf * NT + 3) * TSIZE) * 2;

        #pragma unroll
        for (int ks = 0; ks < KT; ks += 16) {
            uint32_t Af1[2][4], Af2[2][4], Bf[4][4];

            // batched fragment loads: A1 (+A2), then all B1
            #pragma unroll
            for (int mt = 0; mt < 2; mt++)
                LDSM4(Af1[mt][0], Af1[mt][1], Af1[mt][2], Af1[mt][3],
                      tA1 + (a_off + mt * 16 * STRIDE + ks) * 2);
            if (NPROD == 3) {
                #pragma unroll
                for (int mt = 0; mt < 2; mt++)
                    LDSM4(Af2[mt][0], Af2[mt][1], Af2[mt][2], Af2[mt][3],
                          tA2 + (a_off + mt * 16 * STRIDE + ks) * 2);
            }
            #pragma unroll
            for (int p = 0; p < 4; p++)
                LDSM4(Bf[p][0], Bf[p][1], Bf[p][2], Bf[p][3],
                      tB1 + (b_off + p * 16 * STRIDE + ks) * 2);

            // A1*B1 (16 independent MMAs)
            #pragma unroll
            for (int p = 0; p < 4; p++)
                #pragma unroll
                for (int mt = 0; mt < 2; mt++) {
                    MMA16816(acc[mt][p * 2 + 0], Af1[mt], &Bf[p][0]);
                    MMA16816(acc[mt][p * 2 + 1], Af1[mt], &Bf[p][2]);
                }

            if (NPROD == 3) {
                // A2*B1
                #pragma unroll
                for (int p = 0; p < 4; p++)
                    #pragma unroll
                    for (int mt = 0; mt < 2; mt++) {
                        MMA16816(acc[mt][p * 2 + 0], Af2[mt], &Bf[p][0]);
                        MMA16816(acc[mt][p * 2 + 1], Af2[mt], &Bf[p][2]);
                    }
                // reload B2 into the same registers, then A1*B2
                #pragma unroll
                for (int p = 0; p < 4; p++)
                    LDSM4(Bf[p][0], Bf[p][1], Bf[p][2], Bf[p][3],
                          tB2 + (b_off + p * 16 * STRIDE + ks) * 2);
                #pragma unroll
                for (int p = 0; p < 4; p++)
                    #pragma unroll
                    for (int mt = 0; mt < 2; mt++) {
                        MMA16816(acc[mt][p * 2 + 0], Af1[mt], &Bf[p][0]);
                        MMA16816(acc[mt][p * 2 + 1], Af1[mt], &Bf[p][2]);
                    }
            }
        }
        __syncthreads();
    }

    // ---------------- epilogue ----------------
    float rs[2][2] = {{0.f, 0.f}, {0.f, 0.f}};

    #pragma unroll
    for (int mt = 0; mt < 2; mt++) {
        #pragma unroll
        for (int nt = 0; nt < 8; nt++) {
            const int r0 = mBase + mrow + mt * 16 + g;
            const int r1 = r0 + 8;
            const int c  = nBase + ncol + nt * 8 + tig * 2;
            float v0 = acc[mt][nt][0], v1 = acc[mt][nt][1];
            float v2 = acc[mt][nt][2], v3 = acc[mt][nt][3];

            if (MODE == 0) {
                const float b0 = bias[c], b1 = bias[c + 1];
                v0 += b0; v1 += b1; v2 += b0; v3 += b1;
                __half2 h0 = __floats2half2_rn(v0, v1);
                __half2 h1 = __floats2half2_rn(v2, v3);
                float2 f0 = __half22float2(h0), f1 = __half22float2(h1);
                __half2 l0 = __floats2half2_rn(v0 - f0.x, v1 - f0.y);
                __half2 l1 = __floats2half2_rn(v2 - f1.x, v3 - f1.y);
                *(__half2*)(g_th1 + (size_t)r0 * NDIM + c) = h0;
                *(__half2*)(g_th1 + (size_t)r1 * NDIM + c) = h1;
                *(__half2*)(g_th2 + (size_t)r0 * NDIM + c) = l0;
                *(__half2*)(g_th2 + (size_t)r1 * NDIM + c) = l1;
            } else if (MODE == 1) {
                // fast sigmoid -> threshold -> fast exp (MUFU-based, ~1e-6 abs err)
                float a0 = __fdividef(1.f, 1.f + __expf(-v0)); if (a0 < THRESH) a0 = 0.f;
                float a1 = __fdividef(1.f, 1.f + __expf(-v1)); if (a1 < THRESH) a1 = 0.f;
                float a2 = __fdividef(1.f, 1.f + __expf(-v2)); if (a2 < THRESH) a2 = 0.f;
                float a3 = __fdividef(1.f, 1.f + __expf(-v3)); if (a3 < THRESH) a3 = 0.f;
                v0 = __expf(a0); v1 = __expf(a1); v2 = __expf(a2); v3 = __expf(a3);
                rs[mt][0] += v0 + v1;
                rs[mt][1] += v2 + v3;
                *(__half2*)(g_wh + (size_t)r0 * NDIM + c) = __floats2half2_rn(v0, v1);
                *(__half2*)(g_wh + (size_t)r1 * NDIM + c) = __floats2half2_rn(v2, v3);
            } else {
                const float i0 = g_inv[r0], i1 = g_inv[r1];
                *(float2*)(outp + (size_t)r0 * NDIM + c) = make_float2(v0 * i0, v1 * i0);
                *(float2*)(outp + (size_t)r1 * NDIM + c) = make_float2(v2 * i1, v3 * i1);
            }
        }
    }

    if (MODE == 1) {
        #pragma unroll
        for (int mt = 0; mt < 2; mt++)
            #pragma unroll
            for (int h = 0; h < 2; h++) {
                rs[mt][h] += __shfl_xor_sync(0xffffffffu, rs[mt][h], 1);
                rs[mt][h] += __shfl_xor_sync(0xffffffffu, rs[mt][h], 2);
            }
        __syncthreads();
        float* red = (float*)smh;
        if (tig == 0) {
            red[(mrow + g)      * 2 + wn] = rs[0][0];
            red[(mrow + g + 8)  * 2 + wn] = rs[0][1];
            red[(mrow + g + 16) * 2 + wn] = rs[1][0];
            red[(mrow + g + 24) * 2 + wn] = rs[1][1];
        }
        __syncthreads();
        if (tid < 128)
            g_part[(size_t)(mBase + tid) * 64 + blockIdx.x] = red[tid * 2] + red[tid * 2 + 1];
    }
}

// ---------------- elementwise fp32 -> (h1,h2) split ----------------
__global__ void split_k(const float* __restrict__ src,
                        __half* __restrict__ d1, __half* __restrict__ d2, int n4)
{
    const int i = blockIdx.x * 256 + threadIdx.x;
    if (i >= n4) return;
    float4 x = ((const float4*)src)[i];
    __half2 h0 = __floats2half2_rn(x.x, x.y);
    __half2 h1 = __floats2half2_rn(x.z, x.w);
    float2 f0 = __half22float2(h0), f1 = __half22float2(h1);
    __half2 l0 = __floats2half2_rn(x.x - f0.x, x.y - f0.y);
    __half2 l1 = __floats2half2_rn(x.z - f1.x, x.w - f1.y);
    ((uint2*)d1)[i] = make_uint2(*(uint32_t*)&h0, *(uint32_t*)&h1);
    ((uint2*)d2)[i] = make_uint2(*(uint32_t*)&l0, *(uint32_t*)&l1);
}

// ---------------- labels transpose: [LBL][DL] fp32 -> g_lth [DL][LBL] fp16 ----------------
__global__ void transp_k(const float* __restrict__ in)
{
    __shared__ float t[32][33];
    const int bx = blockIdx.x * 32;   // DL dim
    const int by = blockIdx.y * 32;   // LBL dim
    const int x = threadIdx.x, y = threadIdx.y;
    #pragma unroll
    for (int j = 0; j < 32; j += 8)
        t[y + j][x] = in[(size_t)(by + y + j) * DL + bx + x];
    __syncthreads();
    #pragma unroll
    for (int j = 0; j < 32; j += 8)
        g_lth[(size_t)(bx + y + j) * LBL + by + x] = __float2half_rn(t[x][y + j]);
}

// ---------------- row-sum inverse (deterministic) ----------------
__global__ void rowinv_k()
{
    const int m = blockIdx.x * 256 + threadIdx.x;
    float s = 0.f;
    #pragma unroll
    for (int p = 0; p < 32; p++) s += g_part[(size_t)m * 64 + p];
    g_inv[m] = 1.f / s;
}

// ============================ host launcher ============================
#define SMEM_P3 (2 * 4 * 128 * 40 * 2)   // 81920 B  (NPROD=3, KT=32)
#define SMEM_P1 (2 * 2 * 128 * 72 * 2)   // 73728 B  (NPROD=1, KT=64)

extern "C" void kernel_launch(void* const* d_in, const int* in_sizes, int n_in,
                              void* d_out, int out_size)
{
    const float* text   = (const float*)d_in[0];  // [8,2048,1024]
    const float* labels = (const float*)d_in[1];  // [4096,768]
    const float* W      = (const float*)d_in[2];  // [768,1024]
    const float* b      = (const float*)d_in[3];  // [768]
    float* out = (float*)d_out;                   // [8,2048,768]

    __half *xh1, *xh2, *Wh1, *Wh2, *th1, *th2, *lbh1, *lbh2, *wh, *lth;
    cudaGetSymbolAddress((void**)&xh1,  g_xh1);
    cudaGetSymbolAddress((void**)&xh2,  g_xh2);
    cudaGetSymbolAddress((void**)&Wh1,  g_Wh1);
    cudaGetSymbolAddress((void**)&Wh2,  g_Wh2);
    cudaGetSymbolAddress((void**)&th1,  g_th1);
    cudaGetSymbolAddress((void**)&th2,  g_th2);
    cudaGetSymbolAddress((void**)&lbh1, g_lbh1);
    cudaGetSymbolAddress((void**)&lbh2, g_lbh2);
    cudaGetSymbolAddress((void**)&wh,   g_wh);
    cudaGetSymbolAddress((void**)&lth,  g_lth);

    cudaFuncSetAttribute(gemm_async<DT, DL, 32, 3, 0>,
                         cudaFuncAttributeMaxDynamicSharedMemorySize, SMEM_P3);
    cudaFuncSetAttribute(gemm_async<DL, LBL, 32, 3, 1>,
                         cudaFuncAttributeMaxDynamicSharedMemorySize, SMEM_P3);
    cudaFuncSetAttribute(gemm_async<LBL, DL, 64, 1, 2>,
                         cudaFuncAttributeMaxDynamicSharedMemorySize, SMEM_P1);

    // pre-split inputs to fp16 term pairs
    split_k<<<(M_TOTAL * DT / 4 + 255) / 256, 256>>>(text, xh1, xh2, M_TOTAL * DT / 4);
    split_k<<<(DL * DT / 4 + 255) / 256, 256>>>(W, Wh1, Wh2, DL * DT / 4);
    split_k<<<(LBL * DL / 4 + 255) / 256, 256>>>(labels, lbh1, lbh2, LBL * DL / 4);
    transp_k<<<dim3(DL / 32, LBL / 32), dim3(32, 8)>>>(labels);

    // K1: t = text @ W^T + b  (3-product) -> split-stored t
    gemm_async<DT, DL, 32, 3, 0><<<dim3(DL / 128, M_TOTAL / 128), 256, SMEM_P3>>>(
        xh1, xh2, Wh1, Wh2, b, nullptr);

    // K2: w = exp(threshold(sigmoid(t @ labels^T)))  (3-product) -> fp16 + partials
    gemm_async<DL, LBL, 32, 3, 1><<<dim3(LBL / 128, M_TOTAL / 128), 256, SMEM_P3>>>(
        th1, th2, lbh1, lbh2, nullptr, nullptr);

    rowinv_k<<<M_TOTAL / 256, 256>>>();

    // K3: out = (w @ labels) / rowsum  (1-product fp16)
    gemm_async<LBL, DL, 64, 1, 2><<<dim3(DL / 128, M_TOTAL / 128), 256, SMEM_P1>>>(
        wh, nullptr, lth, nullptr, nullptr, out);
}